// round 3
// baseline (speedup 1.0000x reference)
#include <cuda_runtime.h>
#include <cuda_fp16.h>

#define BB    16
#define NN    65536
#define CC    256
#define DINN  16
#define DOUTT 16

__device__ __align__(16) __half g_s[DINN * BB * CC];      // s: [i][b][c], fp16
__device__ __align__(16) float  g_wdt[CC * DOUTT * DINN]; // w_diag: [c][o][i]
__device__ __align__(16) float  g_off[BB * CC * DOUTT];   // off: [b][c][o]

__device__ __forceinline__ float4 shfl_xor_f4(float4 v, int m) {
    v.x = __shfl_xor_sync(0xffffffffu, v.x, m);
    v.y = __shfl_xor_sync(0xffffffffu, v.y, m);
    v.z = __shfl_xor_sync(0xffffffffu, v.z, m);
    v.w = __shfl_xor_sync(0xffffffffu, v.w, m);
    return v;
}
__device__ __forceinline__ float dot4(float4 a, float4 b) {
    return a.x*b.x + a.y*b.y + a.z*b.z + a.w*b.w;
}

// ---------------------------------------------------------------------------
// kT: transpose w_diag [o][i][c] -> [c][o*16+i]
// ---------------------------------------------------------------------------
__global__ __launch_bounds__(256) void kT(const float* __restrict__ wdiag) {
    int idx = blockIdx.x * 256 + threadIdx.x;
    int c  = idx & 255;
    int oi = idx >> 8;
    g_wdt[c * 256 + oi] = wdiag[idx];
}

// ---------------------------------------------------------------------------
// kA: s[i][b][c] = sum_r x[b, pid[c*256+r], i]   (fp16 out)  — unchanged
// ---------------------------------------------------------------------------
__global__ __launch_bounds__(256) void kA(const float* __restrict__ x,
                                          const int* __restrict__ pid) {
    int c = blockIdx.x, b = blockIdx.y;
    __shared__ int ids[256];
    __shared__ float4 red[32];
    int t = threadIdx.x;
    int q = t & 3, g = t >> 2;
    int warp = t >> 5, lane = t & 31;
    ids[t] = pid[c * 256 + t];
    __syncthreads();

    const float* xb = x + (size_t)b * NN * DINN;
    float4 acc = make_float4(0.f, 0.f, 0.f, 0.f);
#pragma unroll
    for (int j = 0; j < 4; j++) {
        int n = ids[g + 64 * j];
        float4 v = ((const float4*)(xb + (size_t)n * DINN))[q];
        acc.x += v.x; acc.y += v.y; acc.z += v.z; acc.w += v.w;
    }
#pragma unroll
    for (int m = 4; m < 32; m <<= 1) {
        float4 o = shfl_xor_f4(acc, m);
        acc.x += o.x; acc.y += o.y; acc.z += o.z; acc.w += o.w;
    }
    if (lane < 4) red[warp * 4 + lane] = acc;
    __syncthreads();
    if (t < 32) {
        float4 v = red[t];
#pragma unroll
        for (int m = 4; m < 32; m <<= 1) {
            float4 o = shfl_xor_f4(v, m);
            v.x += o.x; v.y += o.y; v.z += o.z; v.w += o.w;
        }
        if (t < 4) {
            int i0 = 4 * t;
            g_s[((i0 + 0) * BB + b) * CC + c] = __float2half(v.x);
            g_s[((i0 + 1) * BB + b) * CC + c] = __float2half(v.y);
            g_s[((i0 + 2) * BB + b) * CC + c] = __float2half(v.z);
            g_s[((i0 + 3) * BB + b) * CC + c] = __float2half(v.w);
        }
    }
}

// ---------------------------------------------------------------------------
// kB: off[b][c][o] = (1/N)*sum_{i,k} w_off[o][i][c][k]*s[b][k][i]
// grid (C, 4), 64 threads. Block (c,y) -> o in {4y..4y+3}; warp w -> 2 o's.
// ---------------------------------------------------------------------------
__global__ __launch_bounds__(64) void kB(const float* __restrict__ woff) {
    int c    = blockIdx.x;
    int y    = blockIdx.y;
    int t    = threadIdx.x;
    int w    = t >> 5;
    int lane = t & 31;
    int o0 = 4 * y + 2 * w, o1 = o0 + 1;

    __shared__ __align__(16) __half2 sh[16 * 128];

    __half2 acc0[16], acc1[16];
#pragma unroll
    for (int b = 0; b < 16; b++) {
        acc0[b] = __float2half2_rn(0.f);
        acc1[b] = __float2half2_rn(0.f);
    }

    const uint4* gs4 = (const uint4*)g_s;

    for (int i = 0; i < 16; i++) {
        __syncthreads();
        for (int qq = t; qq < 512; qq += 64)
            ((uint4*)sh)[qq] = gs4[i * 512 + qq];
        __syncthreads();

        const float2* wb0 = (const float2*)(woff + (((size_t)o0 * 16 + i) * CC + c) * CC);
        const float2* wb1 = (const float2*)(woff + (((size_t)o1 * 16 + i) * CC + c) * CC);
#pragma unroll
        for (int stp = 0; stp < 4; stp++) {
            int h = stp * 32 + lane;
            float2 wf0 = wb0[h];
            float2 wf1 = wb1[h];
            __half2 wh0 = __floats2half2_rn(wf0.x, wf0.y);
            __half2 wh1 = __floats2half2_rn(wf1.x, wf1.y);
#pragma unroll
            for (int b = 0; b < 16; b++) {
                __half2 sv = sh[b * 128 + h];
                acc0[b] = __hfma2(wh0, sv, acc0[b]);
                acc1[b] = __hfma2(wh1, sv, acc1[b]);
            }
        }
    }

    const float invN = 1.0f / (float)NN;
#pragma unroll
    for (int b = 0; b < 16; b++) {
        float f0 = __low2float(acc0[b]) + __high2float(acc0[b]);
        float f1 = __low2float(acc1[b]) + __high2float(acc1[b]);
#pragma unroll
        for (int off = 16; off > 0; off >>= 1) {
            f0 += __shfl_xor_sync(0xffffffffu, f0, off);
            f1 += __shfl_xor_sync(0xffffffffu, f1, off);
        }
        if (lane == 0) {
            g_off[((size_t)b * CC + c) * DOUTT + o0] = f0 * invN;
            g_off[((size_t)b * CC + c) * DOUTT + o1] = f1 * invN;
        }
    }
}

// ---------------------------------------------------------------------------
// kC: smem-staged, shuffle-free.
//  phase1: q-split gather of 256 rows -> xs (row stride 20 floats, pad)
//  phase2: thread t computes all 16 outputs of row t; weights via uniform
//          broadcast LDS (unroll 1 on o-groups keeps regs low); res quarters
//          flushed back into xs row t as they are produced
//  phase3: q-split scatter to out
// ---------------------------------------------------------------------------
__global__ __launch_bounds__(256, 4) void kC(const float* __restrict__ x,
                                             const int* __restrict__ pid,
                                             const float* __restrict__ b1,
                                             float* __restrict__ out) {
    int c = blockIdx.x, b = blockIdx.y;
    __shared__ __align__(16) float xs[256 * 20];   // 20 KB, padded rows
    __shared__ __align__(16) float wds[256];
    __shared__ float bsh[16];

    int t = threadIdx.x;
    int q = t & 3, g = t >> 2;

    const int* pc = pid + c * 256;
    int n0 = __ldg(pc + g);
    int n1 = __ldg(pc + g + 64);
    int n2 = __ldg(pc + g + 128);
    int n3 = __ldg(pc + g + 192);

    const float* xb = x + (size_t)b * NN * DINN;
    float4 X0 = ((const float4*)(xb + (size_t)n0 * DINN))[q];
    float4 X1 = ((const float4*)(xb + (size_t)n1 * DINN))[q];
    float4 X2 = ((const float4*)(xb + (size_t)n2 * DINN))[q];
    float4 X3 = ((const float4*)(xb + (size_t)n3 * DINN))[q];

    wds[t] = g_wdt[c * 256 + t];
    if (t < 16) bsh[t] = g_off[((size_t)b * CC + c) * DOUTT + t] + b1[t];

    *(float4*)(xs + (g      ) * 20 + 4 * q) = X0;
    *(float4*)(xs + (g +  64) * 20 + 4 * q) = X1;
    *(float4*)(xs + (g + 128) * 20 + 4 * q) = X2;
    *(float4*)(xs + (g + 192) * 20 + 4 * q) = X3;
    __syncthreads();

    // phase2: own row t
    {
        const float4* xr = (const float4*)(xs + t * 20);
        float4 a0 = xr[0], a1 = xr[1], a2 = xr[2], a3 = xr[3];
        float4* rr = (float4*)(xs + t * 20);
#pragma unroll 1
        for (int og = 0; og < 4; og++) {
            float r[4];
#pragma unroll
            for (int oo = 0; oo < 4; oo++) {
                int o = og * 4 + oo;
                const float4* wr = (const float4*)(wds + o * 16);
                float4 w0 = wr[0], w1 = wr[1], w2 = wr[2], w3 = wr[3];
                r[oo] = bsh[o] + dot4(w0, a0) + dot4(w1, a1)
                               + dot4(w2, a2) + dot4(w3, a3);
            }
            rr[og] = make_float4(r[0], r[1], r[2], r[3]);
        }
    }
    __syncthreads();

    // phase3: q-split scatter
    float* ob = out + (size_t)b * NN * DOUTT;
    float4 R0 = *(const float4*)(xs + (g      ) * 20 + 4 * q);
    float4 R1 = *(const float4*)(xs + (g +  64) * 20 + 4 * q);
    float4 R2 = *(const float4*)(xs + (g + 128) * 20 + 4 * q);
    float4 R3 = *(const float4*)(xs + (g + 192) * 20 + 4 * q);
    ((float4*)(ob + (size_t)n0 * DOUTT))[q] = R0;
    ((float4*)(ob + (size_t)n1 * DOUTT))[q] = R1;
    ((float4*)(ob + (size_t)n2 * DOUTT))[q] = R2;
    ((float4*)(ob + (size_t)n3 * DOUTT))[q] = R3;
}

extern "C" void kernel_launch(void* const* d_in, const int* in_sizes, int n_in,
                              void* d_out, int out_size) {
    const float* x     = (const float*)d_in[0];
    const float* wdiag = (const float*)d_in[1];
    const float* woff  = (const float*)d_in[2];
    const float* b1    = (const float*)d_in[3];
    const int*   pid   = (const int*)d_in[4];
    float* out = (float*)d_out;

    kT<<<256, 256>>>(wdiag);
    kA<<<dim3(CC, BB), 256>>>(x, pid);
    kB<<<dim3(CC, 4), 64>>>(woff);
    kC<<<dim3(CC, BB), 256>>>(x, pid, b1, out);
}

// round 4
// speedup vs baseline: 1.1239x; 1.1239x over previous
#include <cuda_runtime.h>
#include <cuda_fp16.h>

#define BB    16
#define NN    65536
#define CC    256
#define DINN  16
#define DOUTT 16

__device__ __align__(16) __half g_s[DINN * CC * BB];      // s: [i][k][b], fp16
__device__ __align__(16) float  g_wdt[CC * DOUTT * DINN]; // w_diag: [c][o][i]
__device__ __align__(16) float  g_off[BB * CC * DOUTT];   // off: [b][c][o]

__device__ __forceinline__ float4 shfl_xor_f4(float4 v, int m) {
    v.x = __shfl_xor_sync(0xffffffffu, v.x, m);
    v.y = __shfl_xor_sync(0xffffffffu, v.y, m);
    v.z = __shfl_xor_sync(0xffffffffu, v.z, m);
    v.w = __shfl_xor_sync(0xffffffffu, v.w, m);
    return v;
}
__device__ __forceinline__ float dot4(float4 a, float4 b) {
    return a.x*b.x + a.y*b.y + a.z*b.z + a.w*b.w;
}

// ---------------------------------------------------------------------------
// kT: transpose w_diag [o][i][c] -> [c][o*16+i]; zero g_off for kB atomics
// ---------------------------------------------------------------------------
__global__ __launch_bounds__(256) void kT(const float* __restrict__ wdiag) {
    int idx = blockIdx.x * 256 + threadIdx.x;
    int c  = idx & 255;
    int oi = idx >> 8;
    g_wdt[c * 256 + oi] = wdiag[idx];
    g_off[idx] = 0.f;
}

// ---------------------------------------------------------------------------
// kA: s[i][k=c][b] = sum_r x[b, pid[c*256+r], i]   (fp16, b-contiguous)
// ---------------------------------------------------------------------------
__global__ __launch_bounds__(256) void kA(const float* __restrict__ x,
                                          const int* __restrict__ pid) {
    int c = blockIdx.x, b = blockIdx.y;
    __shared__ int ids[256];
    __shared__ float4 red[32];
    int t = threadIdx.x;
    int q = t & 3, g = t >> 2;
    int warp = t >> 5, lane = t & 31;
    ids[t] = pid[c * 256 + t];
    __syncthreads();

    const float* xb = x + (size_t)b * NN * DINN;
    float4 acc = make_float4(0.f, 0.f, 0.f, 0.f);
#pragma unroll
    for (int j = 0; j < 4; j++) {
        int n = ids[g + 64 * j];
        float4 v = ((const float4*)(xb + (size_t)n * DINN))[q];
        acc.x += v.x; acc.y += v.y; acc.z += v.z; acc.w += v.w;
    }
#pragma unroll
    for (int m = 4; m < 32; m <<= 1) {
        float4 o = shfl_xor_f4(acc, m);
        acc.x += o.x; acc.y += o.y; acc.z += o.z; acc.w += o.w;
    }
    if (lane < 4) red[warp * 4 + lane] = acc;
    __syncthreads();
    if (t < 32) {
        float4 v = red[t];
#pragma unroll
        for (int m = 4; m < 32; m <<= 1) {
            float4 o = shfl_xor_f4(v, m);
            v.x += o.x; v.y += o.y; v.z += o.z; v.w += o.w;
        }
        if (t < 4) {
            int i0 = 4 * t;
            g_s[((i0 + 0) * CC + c) * BB + b] = __float2half(v.x);
            g_s[((i0 + 1) * CC + c) * BB + b] = __float2half(v.y);
            g_s[((i0 + 2) * CC + c) * BB + b] = __float2half(v.z);
            g_s[((i0 + 3) * CC + c) * BB + b] = __float2half(v.w);
        }
    }
}

// ---------------------------------------------------------------------------
// kB: off[b][c][o] += (1/N)*sum_{i,k} w_off[o][i][c][k]*s[b][k][i]
// grid (C, 2): y = k-half. 128 threads = 4 warps; warp w -> o in 4w..4w+3.
// Lane owns k = y*128+stp*32+lane; register-caches s[i][k][0..15] (2x128b),
// reuses across 4 o's. No smem, no syncs. g_s is L1/L2 resident (128 KB).
// ---------------------------------------------------------------------------
__global__ __launch_bounds__(128) void kB(const float* __restrict__ woff) {
    int c = blockIdx.x;
    int y = blockIdx.y;
    int w = threadIdx.x >> 5, lane = threadIdx.x & 31;
    int o0 = 4 * w;

    __half2 acc[4][8];
#pragma unroll
    for (int oo = 0; oo < 4; oo++)
#pragma unroll
        for (int bh = 0; bh < 8; bh++) acc[oo][bh] = __float2half2_rn(0.f);

    for (int i = 0; i < 16; i++) {
        const float* wb = woff + (((size_t)(o0 * 16 + i)) * CC + c) * CC + y * 128;
#pragma unroll 2
        for (int stp = 0; stp < 4; stp++) {
            int kk = stp * 32 + lane;
            int k  = y * 128 + kk;
            const uint4* sp = (const uint4*)(g_s + ((size_t)i * CC + k) * BB);
            uint4 sa = sp[0], sb = sp[1];
            __half2 sv[8];
            sv[0] = *(__half2*)&sa.x; sv[1] = *(__half2*)&sa.y;
            sv[2] = *(__half2*)&sa.z; sv[3] = *(__half2*)&sa.w;
            sv[4] = *(__half2*)&sb.x; sv[5] = *(__half2*)&sb.y;
            sv[6] = *(__half2*)&sb.z; sv[7] = *(__half2*)&sb.w;
#pragma unroll
            for (int oo = 0; oo < 4; oo++) {
                float wf = __ldg(wb + (size_t)oo * (16 * CC * CC) + kk);
                __half2 w2 = __half2half2(__float2half(wf));
#pragma unroll
                for (int bh = 0; bh < 8; bh++)
                    acc[oo][bh] = __hfma2(w2, sv[bh], acc[oo][bh]);
            }
        }
    }

    // butterfly reduce over 32 lanes (k dimension)
#pragma unroll
    for (int m = 16; m; m >>= 1)
#pragma unroll
        for (int oo = 0; oo < 4; oo++)
#pragma unroll
            for (int bh = 0; bh < 8; bh++) {
                unsigned u = *reinterpret_cast<unsigned*>(&acc[oo][bh]);
                u = __shfl_xor_sync(0xffffffffu, u, m);
                acc[oo][bh] = __hadd2(acc[oo][bh], *reinterpret_cast<__half2*>(&u));
            }

    if (lane < 8) {
        const float invN = 1.0f / (float)NN;
#pragma unroll
        for (int oo = 0; oo < 4; oo++) {
            float2 f = __half22float2(acc[oo][lane]);
            int o = o0 + oo;
            atomicAdd(&g_off[((size_t)(2 * lane)     * CC + c) * DOUTT + o], f.x * invN);
            atomicAdd(&g_off[((size_t)(2 * lane + 1) * CC + c) * DOUTT + o], f.y * invN);
        }
    }
}

// ---------------------------------------------------------------------------
// kC: R2 shuffle dataflow, sync-free prologue, capped at 85 regs (3 CTAs/SM).
// 4 lanes per row; other quarters via shfl_xor; weights in regs (q^p order).
// ---------------------------------------------------------------------------
__global__ __launch_bounds__(256, 3) void kC(const float* __restrict__ x,
                                             const int* __restrict__ pid,
                                             const float* __restrict__ b1,
                                             float* __restrict__ out) {
    int c = blockIdx.x, b = blockIdx.y;
    int t = threadIdx.x;
    int q = t & 3, g = t >> 2;

    const int* pc = pid + c * 256;
    int ns[4];
    ns[0] = __ldg(pc + g);
    ns[1] = __ldg(pc + g + 64);
    ns[2] = __ldg(pc + g + 128);
    ns[3] = __ldg(pc + g + 192);

    float4 wreg[4][4];
    float  bs[4];
    const float* wc = g_wdt + c * 256;
#pragma unroll
    for (int oo = 0; oo < 4; oo++) {
        int o = 4 * q + oo;
        bs[oo] = __ldg(&g_off[((size_t)b * CC + c) * DOUTT + o]) + __ldg(b1 + o);
#pragma unroll
        for (int p = 0; p < 4; p++)
            wreg[oo][p] = *(const float4*)(wc + o * 16 + 4 * (q ^ p));
    }

    const float* xb = x + (size_t)b * NN * DINN;
    float* ob = out + (size_t)b * NN * DOUTT;

#pragma unroll
    for (int j = 0; j < 4; j++) {
        int n = ns[j];
        float4 X0 = ((const float4*)(xb + (size_t)n * DINN))[q];
        float4 X1 = shfl_xor_f4(X0, 1);
        float4 X2 = shfl_xor_f4(X0, 2);
        float4 X3 = shfl_xor_f4(X0, 3);

        float r0 = bs[0], r1 = bs[1], r2 = bs[2], r3 = bs[3];
        r0 += dot4(wreg[0][0], X0) + dot4(wreg[0][1], X1) + dot4(wreg[0][2], X2) + dot4(wreg[0][3], X3);
        r1 += dot4(wreg[1][0], X0) + dot4(wreg[1][1], X1) + dot4(wreg[1][2], X2) + dot4(wreg[1][3], X3);
        r2 += dot4(wreg[2][0], X0) + dot4(wreg[2][1], X1) + dot4(wreg[2][2], X2) + dot4(wreg[2][3], X3);
        r3 += dot4(wreg[3][0], X0) + dot4(wreg[3][1], X1) + dot4(wreg[3][2], X2) + dot4(wreg[3][3], X3);

        ((float4*)(ob + (size_t)n * DOUTT))[q] = make_float4(r0, r1, r2, r3);
    }
}

extern "C" void kernel_launch(void* const* d_in, const int* in_sizes, int n_in,
                              void* d_out, int out_size) {
    const float* x     = (const float*)d_in[0];
    const float* wdiag = (const float*)d_in[1];
    const float* woff  = (const float*)d_in[2];
    const float* b1    = (const float*)d_in[3];
    const int*   pid   = (const int*)d_in[4];
    float* out = (float*)d_out;

    kT<<<256, 256>>>(wdiag);
    kA<<<dim3(CC, BB), 256>>>(x, pid);
    kB<<<dim3(CC, 2), 128>>>(woff);
    kC<<<dim3(CC, BB), 256>>>(x, pid, b1, out);
}